// round 15
// baseline (speedup 1.0000x reference)
#include <cuda_runtime.h>
#include <cuda_fp16.h>
#include <cstdint>

// KANLinear, round 15: multi-stream pipelined overlap. Kernels byte-identical
// to round 14 (passing) plus a block-offset parameter; rows split into 4
// quarters; afln quarters on the capture stream, GEMM quarters on a forked
// stream gated by events (standard forked-capture pattern, joined at end).
// GEMM (tensor-bound) overlaps afln (FMA/LSU-bound) on disjoint pipes/SMs.

#define NROWS 32768
#define FDIM  512
#define UDIM  512
#define KW     7
#define NKSTEP 224                  // 16-k steps (packed K = 3584)

#define BIG    4
#define NIT    (NKSTEP / BIG)       // 56
#define STG_BYTES 32768             // 16KB A + 16KB B
#define NSTG   3
#define SMEM_TOTAL (NSTG * STG_BYTES)

#define NSPLIT 4
#define AFBLK_PER_Q (2048 / NSPLIT)     // 512 afln blocks per quarter
#define GEMMBY_PER_Q (256 / NSPLIT)     // 64 gemm row-blocks per quarter

__device__ __half g_btf[(size_t)64 * NKSTEP * 32 * 4];    // 3.5 MB B frags
__device__ __half g_af [(size_t)2048 * NKSTEP * 32 * 8];  // 224 MB A frags

#define SIG(L) ((((L) & 3) << 3) | (((L) >> 2) ^ ((((L) & 3) << 1) & 7)))

__device__ __forceinline__ uint32_t smem_u32(const void* p) {
    uint32_t a;
    asm("{ .reg .u64 t; cvta.to.shared.u64 t, %1; cvt.u32.u64 %0, t; }"
        : "=r"(a) : "l"(p));
    return a;
}
#define CP_ASYNC16(dst_u32, src_ptr) \
    asm volatile("cp.async.cg.shared.global [%0], [%1], 16;" \
                 :: "r"(dst_u32), "l"(src_ptr) : "memory")
#define CP_COMMIT() asm volatile("cp.async.commit_group;" ::: "memory")
#define CP_WAIT1()  asm volatile("cp.async.wait_group 1;" ::: "memory")

// ---------------------------------------------------------------------------
// Kernel 1: B fragments, packed K (round-14 verbatim, passing)
// ---------------------------------------------------------------------------
__global__ __launch_bounds__(256) void btf_kernel(const float* __restrict__ Wb,
                                                  const float* __restrict__ Ws) {
    const int n  = blockIdx.x * 256 + threadIdx.x;
    const int ks = blockIdx.y;
    float v[16];
    #pragma unroll
    for (int kk = 0; kk < 16; ++kk) {
        int k = ks * 16 + kk;
        int f = k / KW;
        int m = k - f * KW;
        v[kk] = (m == 0) ? Wb[(size_t)f * UDIM + n]
                         : Ws[(size_t)(f * 6 + m - 1) * UDIM + n];
    }
    __half2* dst = reinterpret_cast<__half2*>(g_btf);
    size_t base = (((size_t)(n >> 3) * NKSTEP + ks) * 32 + (n & 7) * 4) * 2;
    #pragma unroll
    for (int t = 0; t < 4; ++t) {
        dst[base + t * 2 + 0] = __floats2half2_rn(v[2 * t],     v[2 * t + 1]);
        dst[base + t * 2 + 1] = __floats2half2_rn(v[8 + 2 * t], v[8 + 2 * t + 1]);
    }
}

// ---------------------------------------------------------------------------
// closed-form cubic B-spline: 7 values (round-14 verbatim, passing)
// ---------------------------------------------------------------------------
__device__ __forceinline__ void gen7(float xv, float t0, float inv_h, float* v) {
    float xr = (xv - t0) * inv_h;
    float fi = floorf(xr);
    int   i  = (int)fi;
    float s  = xr - fi;
    float s2 = s * s, s3 = s2 * s;
    float u  = 1.0f - s;
    const float c6 = 1.0f / 6.0f;
    float B0 = c6 * u * u * u;
    float B1 = c6 * (3.0f * s3 - 6.0f * s2 + 4.0f);
    float B2 = c6 * (-3.0f * s3 + 3.0f * s2 + 3.0f * s + 1.0f);
    float B3 = c6 * s3;
    bool valid = (xr >= 0.0f) && (i <= 8);
    v[0] = fmaxf(xv, 0.0f);
    #pragma unroll
    for (int j = 0; j < 6; ++j) {
        int d = i - j;
        float bv = (d == 3) ? B0 : (d == 2) ? B1 : (d == 1) ? B2 : (d == 0) ? B3 : 0.0f;
        v[1 + j] = valid ? bv : 0.0f;
    }
}

// ---------------------------------------------------------------------------
// Kernel 2: fused LN + packed A fragments (round-14 verbatim + block offset)
// ---------------------------------------------------------------------------
__global__ __launch_bounds__(256) void afln_kernel(
    const float* __restrict__ x,
    const float* __restrict__ gamma,
    const float* __restrict__ beta,
    const float* __restrict__ grid_knots,
    int blk0)
{
    __shared__ float sx[16][514];
    __shared__ float sg[512], sb[512];
    __shared__ float smean[16], sinv[16];
    __shared__ __align__(16) __half sstg[8][16 * 116];

    const int bx   = blockIdx.x + blk0;
    const int tid  = threadIdx.x;
    const int lane = tid & 31;
    const int wq   = tid >> 5;
    const int R0   = bx * 16;

    const float t0    = __ldg(grid_knots);
    const float inv_h = 1.0f / (__ldg(grid_knots + 1) - t0);

    for (int idx = tid; idx < 16 * 128; idx += 256) {
        int row = idx >> 7, q = idx & 127;
        float4 v = __ldg(reinterpret_cast<const float4*>(
            x + (size_t)(R0 + row) * FDIM) + q);
        *reinterpret_cast<float2*>(&sx[row][q * 4])     = make_float2(v.x, v.y);
        *reinterpret_cast<float2*>(&sx[row][q * 4 + 2]) = make_float2(v.z, v.w);
    }
    for (int idx = tid; idx < 512; idx += 256) {
        sg[idx] = __ldg(gamma + idx);
        sb[idx] = __ldg(beta + idx);
    }
    __syncthreads();

    #pragma unroll
    for (int rr = 0; rr < 2; ++rr) {
        int r = wq * 2 + rr;
        float s = 0.0f;
        #pragma unroll
        for (int i = 0; i < 16; ++i) s += sx[r][lane + 32 * i];
        #pragma unroll
        for (int o = 16; o > 0; o >>= 1) s += __shfl_xor_sync(~0u, s, o);
        float mean = s * (1.0f / FDIM);
        float s2 = 0.0f;
        #pragma unroll
        for (int i = 0; i < 16; ++i) {
            float d = sx[r][lane + 32 * i] - mean;
            s2 += d * d;
        }
        #pragma unroll
        for (int o = 16; o > 0; o >>= 1) s2 += __shfl_xor_sync(~0u, s2, o);
        if (lane == 0) {
            smean[r] = mean;
            sinv[r]  = rsqrtf(s2 * (1.0f / FDIM) + 1e-3f);
        }
    }
    __syncthreads();

    const int rl = lane & 15;
    const int ph = lane >> 4;
    const int g7 = lane >> 2;
    const int tq = lane & 3;
    const float mean = smean[rl];
    const float inv  = sinv[rl];

    __half* stg = &sstg[wq][rl * 116];
    const __half* stgW = sstg[wq];
    uint4* dstB = reinterpret_cast<uint4*>(g_af) +
                  (size_t)bx * NKSTEP * 32 + SIG(lane);

    #pragma unroll 1
    for (int g = wq; g < 32; g += 8) {
        #pragma unroll
        for (int q = 0; q < 4; ++q) {
            int fp  = q * 4 + ph * 2;
            int col = g * 16 + fp;
            float xa = (sx[rl][col]     - mean) * inv * sg[col]     + sb[col];
            float xb = (sx[rl][col + 1] - mean) * inv * sg[col + 1] + sb[col + 1];
            float va[7], vb[7];
            gen7(xa, t0, inv_h, va);
            gen7(xb, t0, inv_h, vb);
            __half2* w = reinterpret_cast<__half2*>(stg + fp * KW);
            w[0] = __floats2half2_rn(va[0], va[1]);
            w[1] = __floats2half2_rn(va[2], va[3]);
            w[2] = __floats2half2_rn(va[4], va[5]);
            w[3] = __floats2half2_rn(va[6], vb[0]);
            w[4] = __floats2half2_rn(vb[1], vb[2]);
            w[5] = __floats2half2_rn(vb[3], vb[4]);
            w[6] = __floats2half2_rn(vb[5], vb[6]);
        }
        __syncwarp();
        #pragma unroll
        for (int j = 0; j < KW; ++j) {
            int kl = j * 16 + 2 * tq;
            uint32_t w0 = *reinterpret_cast<const uint32_t*>(&stgW[g7 * 116 + kl]);
            uint32_t w1 = *reinterpret_cast<const uint32_t*>(&stgW[(g7 + 8) * 116 + kl]);
            uint32_t w2 = *reinterpret_cast<const uint32_t*>(&stgW[g7 * 116 + kl + 8]);
            uint32_t w3 = *reinterpret_cast<const uint32_t*>(&stgW[(g7 + 8) * 116 + kl + 8]);
            dstB[(size_t)(g * KW + j) * 32] = make_uint4(w0, w1, w2, w3);
        }
        __syncwarp();
    }
}

// ---------------------------------------------------------------------------
// Kernel 3: cp.async 3-stage pipelined HMMA GEMM (round-14 verbatim + by0)
// ---------------------------------------------------------------------------
__global__ __launch_bounds__(256, 2) void kan_mma_kernel(
    const float* __restrict__ bias, float* __restrict__ out, int by0)
{
    extern __shared__ __align__(16) char smem[];
    const uint32_t sbase = smem_u32(smem);

    const int tid  = threadIdx.x;
    const int lane = tid & 31;
    const int wid  = tid >> 5;
    const int wm   = wid >> 2;
    const int wn   = wid & 3;
    const int by   = blockIdx.y + by0;
    const int row0 = by * 128;
    const int col0 = blockIdx.x * 128;

    const uint4* agm = reinterpret_cast<const uint4*>(g_af);
    const uint4* bgm = reinterpret_cast<const uint4*>(g_btf);
    const size_t arow0 = (size_t)by * 8;
    const size_t brow0 = (size_t)blockIdx.x * 16;

    auto issue_stage = [&](int stg, int ks0) {
        const uint32_t da = sbase + stg * STG_BYTES;
        const uint32_t db = da + 16384;
        #pragma unroll
        for (int r = 0; r < 4; ++r) {
            int q = tid + r * 256;
            const uint4* srcA = agm +
                ((arow0 + (q >> 7)) * NKSTEP + ks0 + ((q >> 5) & 3)) * 32 + (q & 31);
            CP_ASYNC16(da + q * 16, srcA);
        }
        #pragma unroll
        for (int r = 0; r < 4; ++r) {
            int q = tid + r * 256;
            const uint4* srcB = bgm +
                ((brow0 + (q >> 6)) * NKSTEP + ks0 + ((q >> 4) & 3)) * 16 + (q & 15);
            CP_ASYNC16(db + q * 16, srcB);
        }
        CP_COMMIT();
    };

    float acc[4][4][4];
    #pragma unroll
    for (int in = 0; in < 4; ++in) {
        float2 bb = *reinterpret_cast<const float2*>(
            bias + col0 + wn * 32 + in * 8 + (lane & 3) * 2);
        #pragma unroll
        for (int im = 0; im < 4; ++im) {
            acc[im][in][0] = bb.x; acc[im][in][1] = bb.y;
            acc[im][in][2] = bb.x; acc[im][in][3] = bb.y;
        }
    }

    issue_stage(0, 0);
    issue_stage(1, BIG);

    const int aslot = SIG(lane);
    int stg = 0;
    for (int it = 0; it < NIT; ++it) {
        CP_WAIT1();
        __syncthreads();
        if (it + 2 < NIT) issue_stage((stg + 2) % NSTG, (it + 2) * BIG);

        const char* sa = smem + stg * STG_BYTES;
        const char* sb = sa + 16384;
        #pragma unroll
        for (int ks = 0; ks < BIG; ++ks) {
            uint4 a[4];
            #pragma unroll
            for (int im = 0; im < 4; ++im)
                a[im] = *reinterpret_cast<const uint4*>(
                    sa + (((wm * 4 + im) * 4 + ks) * 32 + aslot) * 16);
            uint2 b[4];
            #pragma unroll
            for (int in = 0; in < 4; ++in)
                b[in] = *reinterpret_cast<const uint2*>(
                    sb + (((wn * 4 + in) * 4 + ks) * 32 + lane) * 8);
            #pragma unroll
            for (int im = 0; im < 4; ++im)
                #pragma unroll
                for (int in = 0; in < 4; ++in) {
                    asm volatile(
                        "mma.sync.aligned.m16n8k16.row.col.f32.f16.f16.f32 "
                        "{%0,%1,%2,%3}, {%4,%5,%6,%7}, {%8,%9}, {%0,%1,%2,%3};"
                        : "+f"(acc[im][in][0]), "+f"(acc[im][in][1]),
                          "+f"(acc[im][in][2]), "+f"(acc[im][in][3])
                        : "r"(a[im].x), "r"(a[im].y), "r"(a[im].z), "r"(a[im].w),
                          "r"(b[in].x), "r"(b[in].y));
                }
        }
        stg = (stg + 1) % NSTG;
    }

    const int g  = lane >> 2;
    const int tq = lane & 3;
    #pragma unroll
    for (int im = 0; im < 4; ++im) {
        int row = row0 + wm * 64 + im * 16 + g;
        #pragma unroll
        for (int in = 0; in < 4; ++in) {
            int col = col0 + wn * 32 + in * 8 + tq * 2;
            *reinterpret_cast<float2*>(out + (size_t)row * UDIM + col)
                = make_float2(acc[im][in][0], acc[im][in][1]);
            *reinterpret_cast<float2*>(out + (size_t)(row + 8) * UDIM + col)
                = make_float2(acc[im][in][2], acc[im][in][3]);
        }
    }
}

// ---------------------------------------------------------------------------
extern "C" void kernel_launch(void* const* d_in, const int* in_sizes, int n_in,
                              void* d_out, int out_size) {
    const float* x     = (const float*)d_in[0];
    const float* gamma = (const float*)d_in[1];
    const float* beta  = (const float*)d_in[2];
    const float* Wb    = (const float*)d_in[3];
    const float* bias  = (const float*)d_in[4];
    const float* Ws    = (const float*)d_in[5];
    const float* grid  = (const float*)d_in[6];
    float* out = (float*)d_out;

    // one-time infrastructure (handles only; per-call work is identical)
    static cudaStream_t s1 = nullptr;
    static cudaEvent_t evq[NSPLIT], evjoin;
    if (s1 == nullptr) {
        cudaStreamCreateWithFlags(&s1, cudaStreamNonBlocking);
        for (int q = 0; q < NSPLIT; ++q)
            cudaEventCreateWithFlags(&evq[q], cudaEventDisableTiming);
        cudaEventCreateWithFlags(&evjoin, cudaEventDisableTiming);
        cudaFuncSetAttribute(kan_mma_kernel,
                             cudaFuncAttributeMaxDynamicSharedMemorySize,
                             SMEM_TOTAL);
    }

    btf_kernel<<<dim3(2, NKSTEP), 256>>>(Wb, Ws);
    for (int q = 0; q < NSPLIT; ++q) {
        afln_kernel<<<AFBLK_PER_Q, 256>>>(x, gamma, beta, grid,
                                          q * AFBLK_PER_Q);
        cudaEventRecord(evq[q], 0);
        cudaStreamWaitEvent(s1, evq[q], 0);
        kan_mma_kernel<<<dim3(UDIM / 128, GEMMBY_PER_Q), 256, SMEM_TOTAL, s1>>>(
            bias, out, q * GEMMBY_PER_Q);
    }
    cudaEventRecord(evjoin, s1);
    cudaStreamWaitEvent(0, evjoin, 0);
}

// round 16
// speedup vs baseline: 1.0087x; 1.0087x over previous
#include <cuda_runtime.h>
#include <cuda_fp16.h>
#include <cstdint>

// KANLinear, round 16: GEMM loads via cp.async.bulk + mbarrier (kills the
// LDGSTS-issue floor: 2048 cp.async/iter/CTA -> 24 bulk copies). afln/btf
// round-14 verbatim; btf forked onto a side stream (overlaps afln start).

#define NROWS 32768
#define FDIM  512
#define UDIM  512
#define KW     7
#define NKSTEP 224                  // 16-k steps (packed K = 3584)

#define BIG    4
#define NIT    (NKSTEP / BIG)       // 56
#define STG_BYTES 32768             // 16KB A + 16KB B
#define NSTG   3
#define SM_MBAR   (NSTG * STG_BYTES)
#define SMEM_TOTAL (SM_MBAR + 128)

__device__ __align__(128) __half g_btf[(size_t)64 * NKSTEP * 32 * 4];   // 3.5 MB
__device__ __align__(128) __half g_af [(size_t)2048 * NKSTEP * 32 * 8]; // 224 MB

#define SIG(L) ((((L) & 3) << 3) | (((L) >> 2) ^ ((((L) & 3) << 1) & 7)))

__device__ __forceinline__ uint32_t smem_u32(const void* p) {
    uint32_t a;
    asm("{ .reg .u64 t; cvta.to.shared.u64 t, %1; cvt.u32.u64 %0, t; }"
        : "=r"(a) : "l"(p));
    return a;
}
#define MBAR_INIT(a, c) \
    asm volatile("mbarrier.init.shared.b64 [%0], %1;" :: "r"(a), "r"(c) : "memory")
#define MBAR_EXPECT_TX(a, bytes) \
    asm volatile("mbarrier.arrive.expect_tx.shared.b64 _, [%0], %1;" \
                 :: "r"(a), "r"(bytes) : "memory")
#define MBAR_WAIT(a, ph) do {                                                  \
    uint32_t _m = (a), _p = (ph), _d;                                          \
    asm volatile("{ .reg .pred p;"                                             \
        "mbarrier.try_wait.parity.acquire.cta.shared::cta.b64 p, [%1], %2;"    \
        "selp.b32 %0,1,0,p; }" : "=r"(_d) : "r"(_m), "r"(_p) : "memory");      \
    if (!_d) {                                                                 \
        asm volatile("{ .reg .pred P1; WL_%=:"                                 \
            "mbarrier.try_wait.parity.acquire.cta.shared::cta.b64 P1, [%0], %1, 0x989680;" \
            "@P1 bra.uni WD_%=; bra.uni WL_%=; WD_%=: }"                       \
            :: "r"(_m), "r"(_p) : "memory");                                   \
    }                                                                          \
} while (0)
#define FENCE_ASYNC() asm volatile("fence.proxy.async.shared::cta;" ::: "memory")
#define CP_BULK(dst_u32, src_ptr, sz, mbar_u32) \
    asm volatile("cp.async.bulk.shared::cluster.global.mbarrier::complete_tx::bytes " \
                 "[%0], [%1], %2, [%3];" \
                 :: "r"(dst_u32), "l"(src_ptr), "r"(sz), "r"(mbar_u32) : "memory")

// ---------------------------------------------------------------------------
// Kernel 1: B fragments, packed K (round-14 verbatim, passing)
// ---------------------------------------------------------------------------
__global__ __launch_bounds__(256) void btf_kernel(const float* __restrict__ Wb,
                                                  const float* __restrict__ Ws) {
    const int n  = blockIdx.x * 256 + threadIdx.x;
    const int ks = blockIdx.y;
    float v[16];
    #pragma unroll
    for (int kk = 0; kk < 16; ++kk) {
        int k = ks * 16 + kk;
        int f = k / KW;
        int m = k - f * KW;
        v[kk] = (m == 0) ? Wb[(size_t)f * UDIM + n]
                         : Ws[(size_t)(f * 6 + m - 1) * UDIM + n];
    }
    __half2* dst = reinterpret_cast<__half2*>(g_btf);
    size_t base = (((size_t)(n >> 3) * NKSTEP + ks) * 32 + (n & 7) * 4) * 2;
    #pragma unroll
    for (int t = 0; t < 4; ++t) {
        dst[base + t * 2 + 0] = __floats2half2_rn(v[2 * t],     v[2 * t + 1]);
        dst[base + t * 2 + 1] = __floats2half2_rn(v[8 + 2 * t], v[8 + 2 * t + 1]);
    }
}

// ---------------------------------------------------------------------------
// closed-form cubic B-spline: 7 values (round-14 verbatim, passing)
// ---------------------------------------------------------------------------
__device__ __forceinline__ void gen7(float xv, float t0, float inv_h, float* v) {
    float xr = (xv - t0) * inv_h;
    float fi = floorf(xr);
    int   i  = (int)fi;
    float s  = xr - fi;
    float s2 = s * s, s3 = s2 * s;
    float u  = 1.0f - s;
    const float c6 = 1.0f / 6.0f;
    float B0 = c6 * u * u * u;
    float B1 = c6 * (3.0f * s3 - 6.0f * s2 + 4.0f);
    float B2 = c6 * (-3.0f * s3 + 3.0f * s2 + 3.0f * s + 1.0f);
    float B3 = c6 * s3;
    bool valid = (xr >= 0.0f) && (i <= 8);
    v[0] = fmaxf(xv, 0.0f);
    #pragma unroll
    for (int j = 0; j < 6; ++j) {
        int d = i - j;
        float bv = (d == 3) ? B0 : (d == 2) ? B1 : (d == 1) ? B2 : (d == 0) ? B3 : 0.0f;
        v[1 + j] = valid ? bv : 0.0f;
    }
}

// ---------------------------------------------------------------------------
// Kernel 2: fused LN + packed A fragments (round-14 verbatim, passing)
// ---------------------------------------------------------------------------
__global__ __launch_bounds__(256) void afln_kernel(
    const float* __restrict__ x,
    const float* __restrict__ gamma,
    const float* __restrict__ beta,
    const float* __restrict__ grid_knots)
{
    __shared__ float sx[16][514];
    __shared__ float sg[512], sb[512];
    __shared__ float smean[16], sinv[16];
    __shared__ __align__(16) __half sstg[8][16 * 116];

    const int tid  = threadIdx.x;
    const int lane = tid & 31;
    const int wq   = tid >> 5;
    const int R0   = blockIdx.x * 16;

    const float t0    = __ldg(grid_knots);
    const float inv_h = 1.0f / (__ldg(grid_knots + 1) - t0);

    for (int idx = tid; idx < 16 * 128; idx += 256) {
        int row = idx >> 7, q = idx & 127;
        float4 v = __ldg(reinterpret_cast<const float4*>(
            x + (size_t)(R0 + row) * FDIM) + q);
        *reinterpret_cast<float2*>(&sx[row][q * 4])     = make_float2(v.x, v.y);
        *reinterpret_cast<float2*>(&sx[row][q * 4 + 2]) = make_float2(v.z, v.w);
    }
    for (int idx = tid; idx < 512; idx += 256) {
        sg[idx] = __ldg(gamma + idx);
        sb[idx] = __ldg(beta + idx);
    }
    __syncthreads();

    #pragma unroll
    for (int rr = 0; rr < 2; ++rr) {
        int r = wq * 2 + rr;
        float s = 0.0f;
        #pragma unroll
        for (int i = 0; i < 16; ++i) s += sx[r][lane + 32 * i];
        #pragma unroll
        for (int o = 16; o > 0; o >>= 1) s += __shfl_xor_sync(~0u, s, o);
        float mean = s * (1.0f / FDIM);
        float s2 = 0.0f;
        #pragma unroll
        for (int i = 0; i < 16; ++i) {
            float d = sx[r][lane + 32 * i] - mean;
            s2 += d * d;
        }
        #pragma unroll
        for (int o = 16; o > 0; o >>= 1) s2 += __shfl_xor_sync(~0u, s2, o);
        if (lane == 0) {
            smean[r] = mean;
            sinv[r]  = rsqrtf(s2 * (1.0f / FDIM) + 1e-3f);
        }
    }
    __syncthreads();

    const int rl = lane & 15;
    const int ph = lane >> 4;
    const int g7 = lane >> 2;
    const int tq = lane & 3;
    const float mean = smean[rl];
    const float inv  = sinv[rl];

    __half* stg = &sstg[wq][rl * 116];
    const __half* stgW = sstg[wq];
    uint4* dstB = reinterpret_cast<uint4*>(g_af) +
                  (size_t)blockIdx.x * NKSTEP * 32 + SIG(lane);

    #pragma unroll 1
    for (int g = wq; g < 32; g += 8) {
        #pragma unroll
        for (int q = 0; q < 4; ++q) {
            int fp  = q * 4 + ph * 2;
            int col = g * 16 + fp;
            float xa = (sx[rl][col]     - mean) * inv * sg[col]     + sb[col];
            float xb = (sx[rl][col + 1] - mean) * inv * sg[col + 1] + sb[col + 1];
            float va[7], vb[7];
            gen7(xa, t0, inv_h, va);
            gen7(xb, t0, inv_h, vb);
            __half2* w = reinterpret_cast<__half2*>(stg + fp * KW);
            w[0] = __floats2half2_rn(va[0], va[1]);
            w[1] = __floats2half2_rn(va[2], va[3]);
            w[2] = __floats2half2_rn(va[4], va[5]);
            w[3] = __floats2half2_rn(va[6], vb[0]);
            w[4] = __floats2half2_rn(vb[1], vb[2]);
            w[5] = __floats2half2_rn(vb[3], vb[4]);
            w[6] = __floats2half2_rn(vb[5], vb[6]);
        }
        __syncwarp();
        #pragma unroll
        for (int j = 0; j < KW; ++j) {
            int kl = j * 16 + 2 * tq;
            uint32_t w0 = *reinterpret_cast<const uint32_t*>(&stgW[g7 * 116 + kl]);
            uint32_t w1 = *reinterpret_cast<const uint32_t*>(&stgW[(g7 + 8) * 116 + kl]);
            uint32_t w2 = *reinterpret_cast<const uint32_t*>(&stgW[g7 * 116 + kl + 8]);
            uint32_t w3 = *reinterpret_cast<const uint32_t*>(&stgW[(g7 + 8) * 116 + kl + 8]);
            dstB[(size_t)(g * KW + j) * 32] = make_uint4(w0, w1, w2, w3);
        }
        __syncwarp();
    }
}

// ---------------------------------------------------------------------------
// Kernel 3: bulk-copy 3-stage pipelined HMMA GEMM.
// Stage fill = 8 A-chunks (2KB) + 16 B-chunks (1KB) via cp.async.bulk,
// expect_tx 32KB on the stage mbarrier; consumers try_wait.parity.acquire.
// mma loop / smem layout / epilogue identical to round 14.
// ---------------------------------------------------------------------------
__global__ __launch_bounds__(256, 2) void kan_mma_kernel(
    const float* __restrict__ bias, float* __restrict__ out)
{
    extern __shared__ __align__(16) char smem[];
    const uint32_t sbase = smem_u32(smem);

    const int tid  = threadIdx.x;
    const int lane = tid & 31;
    const int wid  = tid >> 5;
    const int wm   = wid >> 2;
    const int wn   = wid & 3;
    const int row0 = blockIdx.y * 128;
    const int col0 = blockIdx.x * 128;

    const char* agm = reinterpret_cast<const char*>(g_af);
    const char* bgm = reinterpret_cast<const char*>(g_btf);
    const size_t arow0 = (size_t)blockIdx.y * 8;
    const size_t brow0 = (size_t)blockIdx.x * 16;

    // mbarrier init
    if (tid == 0) {
        #pragma unroll
        for (int s = 0; s < NSTG; ++s) MBAR_INIT(sbase + SM_MBAR + s * 8, 1);
        FENCE_ASYNC();
    }
    __syncthreads();

    // stage fill: tid0 arms expect_tx; lane0 of each warp issues 3 bulk copies
    auto issue_stage = [&](int stg, int ks0) {
        const uint32_t mb = sbase + SM_MBAR + stg * 8;
        const uint32_t da = sbase + stg * STG_BYTES;
        const uint32_t db = da + 16384;
        if (tid == 0) MBAR_EXPECT_TX(mb, STG_BYTES);
        if (lane == 0) {
            // A chunk mt = wid (2KB)
            const char* srcA = agm + ((arow0 + wid) * NKSTEP + ks0) * 512;
            CP_BULK(da + wid * 2048, srcA, 2048, mb);
            // B chunks nt = 2wid, 2wid+1 (1KB each)
            #pragma unroll
            for (int h = 0; h < 2; ++h) {
                int nt = wid * 2 + h;
                const char* srcB = bgm + ((brow0 + nt) * NKSTEP + ks0) * 256;
                CP_BULK(db + nt * 1024, srcB, 1024, mb);
            }
        }
    };

    float acc[4][4][4];
    #pragma unroll
    for (int in = 0; in < 4; ++in) {
        float2 bb = *reinterpret_cast<const float2*>(
            bias + col0 + wn * 32 + in * 8 + (lane & 3) * 2);
        #pragma unroll
        for (int im = 0; im < 4; ++im) {
            acc[im][in][0] = bb.x; acc[im][in][1] = bb.y;
            acc[im][in][2] = bb.x; acc[im][in][3] = bb.y;
        }
    }

    issue_stage(0, 0);
    issue_stage(1, BIG);

    const int aslot = SIG(lane);
    int phs[NSTG] = {0, 0, 0};
    int stg = 0;
    for (int it = 0; it < NIT; ++it) {
        MBAR_WAIT(sbase + SM_MBAR + stg * 8, phs[stg]);
        phs[stg] ^= 1;

        const char* sa = smem + stg * STG_BYTES;
        const char* sb = sa + 16384;
        #pragma unroll
        for (int ks = 0; ks < BIG; ++ks) {
            uint4 a[4];
            #pragma unroll
            for (int im = 0; im < 4; ++im)
                a[im] = *reinterpret_cast<const uint4*>(
                    sa + (((wm * 4 + im) * 4 + ks) * 32 + aslot) * 16);
            uint2 b[4];
            #pragma unroll
            for (int in = 0; in < 4; ++in)
                b[in] = *reinterpret_cast<const uint2*>(
                    sb + (((wn * 4 + in) * 4 + ks) * 32 + lane) * 8);
            #pragma unroll
            for (int im = 0; im < 4; ++im)
                #pragma unroll
                for (int in = 0; in < 4; ++in) {
                    asm volatile(
                        "mma.sync.aligned.m16n8k16.row.col.f32.f16.f16.f32 "
                        "{%0,%1,%2,%3}, {%4,%5,%6,%7}, {%8,%9}, {%0,%1,%2,%3};"
                        : "+f"(acc[im][in][0]), "+f"(acc[im][in][1]),
                          "+f"(acc[im][in][2]), "+f"(acc[im][in][3])
                        : "r"(a[im].x), "r"(a[im].y), "r"(a[im].z), "r"(a[im].w),
                          "r"(b[in].x), "r"(b[in].y));
                }
        }

        __syncthreads();   // all warps done reading stage (stg+2)%3's old data
        if (it + 2 < NIT) issue_stage((stg + 2) % NSTG, (it + 2) * BIG);
        stg = (stg + 1) % NSTG;
    }

    const int g  = lane >> 2;
    const int tq = lane & 3;
    #pragma unroll
    for (int im = 0; im < 4; ++im) {
        int row = row0 + wm * 64 + im * 16 + g;
        #pragma unroll
        for (int in = 0; in < 4; ++in) {
            int col = col0 + wn * 32 + in * 8 + tq * 2;
            *reinterpret_cast<float2*>(out + (size_t)row * UDIM + col)
                = make_float2(acc[im][in][0], acc[im][in][1]);
            *reinterpret_cast<float2*>(out + (size_t)(row + 8) * UDIM + col)
                = make_float2(acc[im][in][2], acc[im][in][3]);
        }
    }
}

// ---------------------------------------------------------------------------
extern "C" void kernel_launch(void* const* d_in, const int* in_sizes, int n_in,
                              void* d_out, int out_size) {
    const float* x     = (const float*)d_in[0];
    const float* gamma = (const float*)d_in[1];
    const float* beta  = (const float*)d_in[2];
    const float* Wb    = (const float*)d_in[3];
    const float* bias  = (const float*)d_in[4];
    const float* Ws    = (const float*)d_in[5];
    const float* grid  = (const float*)d_in[6];
    float* out = (float*)d_out;

    static cudaStream_t s1 = nullptr;
    static cudaEvent_t ev0, evb;
    if (s1 == nullptr) {
        cudaStreamCreateWithFlags(&s1, cudaStreamNonBlocking);
        cudaEventCreateWithFlags(&ev0, cudaEventDisableTiming);
        cudaEventCreateWithFlags(&evb, cudaEventDisableTiming);
        cudaFuncSetAttribute(kan_mma_kernel,
                             cudaFuncAttributeMaxDynamicSharedMemorySize,
                             SMEM_TOTAL);
    }

    // fork: btf runs on s1 concurrently with afln on the main stream
    cudaEventRecord(ev0, 0);
    cudaStreamWaitEvent(s1, ev0, 0);
    btf_kernel<<<dim3(2, NKSTEP), 256, 0, s1>>>(Wb, Ws);
    cudaEventRecord(evb, s1);

    afln_kernel<<<NROWS / 16, 256>>>(x, gamma, beta, grid);

    // join: GEMM needs both afln (stream 0) and btf (s1)
    cudaStreamWaitEvent(0, evb, 0);
    kan_mma_kernel<<<dim3(UDIM / 128, NROWS / 128), 256, SMEM_TOTAL>>>(bias, out);
}

// round 17
// speedup vs baseline: 1.1248x; 1.1151x over previous
#include <cuda_runtime.h>
#include <cuda_fp16.h>
#include <cstdint>

// KANLinear, round 17: stage-contiguous fragment layouts so the GEMM loads
// each 32KB stage with exactly TWO 16KB cp.async.bulk copies issued by one
// thread (removes the 8192 cyc/iter LDGSTS-issue floor of the cp.async path
// and the 24-small-copy overhead of round 16).
//  g_af : [by 256][ks 224][mt 8][512B]   (stage A = 16KB contiguous)
//  g_btf: [bxn 4][ks 224][nt 16][256B]   (stage B = 16KB contiguous)
// mma reads use [ks][mt]/[ks][nt] smem indexing — same bytes, same k order.

#define NROWS 32768
#define FDIM  512
#define UDIM  512
#define KW     7
#define NKSTEP 224                  // 16-k steps (packed K = 3584)

#define BIG    4
#define NIT    (NKSTEP / BIG)       // 56
#define STG_BYTES 32768             // 16KB A + 16KB B
#define NSTG   3
#define SM_MBAR   (NSTG * STG_BYTES)
#define SMEM_TOTAL (SM_MBAR + 128)

__device__ __align__(128) __half g_btf[(size_t)4 * NKSTEP * 16 * 128];   // 3.5 MB
__device__ __align__(128) __half g_af [(size_t)256 * NKSTEP * 8 * 256];  // 224 MB

#define SIG(L) ((((L) & 3) << 3) | (((L) >> 2) ^ ((((L) & 3) << 1) & 7)))

__device__ __forceinline__ uint32_t smem_u32(const void* p) {
    uint32_t a;
    asm("{ .reg .u64 t; cvta.to.shared.u64 t, %1; cvt.u32.u64 %0, t; }"
        : "=r"(a) : "l"(p));
    return a;
}
#define MBAR_INIT(a, c) \
    asm volatile("mbarrier.init.shared.b64 [%0], %1;" :: "r"(a), "r"(c) : "memory")
#define MBAR_EXPECT_TX(a, bytes) \
    asm volatile("mbarrier.arrive.expect_tx.shared.b64 _, [%0], %1;" \
                 :: "r"(a), "r"(bytes) : "memory")
#define MBAR_WAIT(a, ph) do {                                                  \
    uint32_t _m = (a), _p = (ph), _d;                                          \
    asm volatile("{ .reg .pred p;"                                             \
        "mbarrier.try_wait.parity.acquire.cta.shared::cta.b64 p, [%1], %2;"    \
        "selp.b32 %0,1,0,p; }" : "=r"(_d) : "r"(_m), "r"(_p) : "memory");      \
    if (!_d) {                                                                 \
        asm volatile("{ .reg .pred P1; WL_%=:"                                 \
            "mbarrier.try_wait.parity.acquire.cta.shared::cta.b64 P1, [%0], %1, 0x989680;" \
            "@P1 bra.uni WD_%=; bra.uni WL_%=; WD_%=: }"                       \
            :: "r"(_m), "r"(_p) : "memory");                                   \
    }                                                                          \
} while (0)
#define FENCE_ASYNC() asm volatile("fence.proxy.async.shared::cta;" ::: "memory")
#define CP_BULK(dst_u32, src_ptr, sz, mbar_u32) \
    asm volatile("cp.async.bulk.shared::cluster.global.mbarrier::complete_tx::bytes " \
                 "[%0], [%1], %2, [%3];" \
                 :: "r"(dst_u32), "l"(src_ptr), "r"(sz), "r"(mbar_u32) : "memory")

// ---------------------------------------------------------------------------
// Kernel 1: B fragments, packed K, stage-contiguous layout.
// ---------------------------------------------------------------------------
__global__ __launch_bounds__(256) void btf_kernel(const float* __restrict__ Wb,
                                                  const float* __restrict__ Ws) {
    const int n  = blockIdx.x * 256 + threadIdx.x;
    const int ks = blockIdx.y;
    float v[16];
    #pragma unroll
    for (int kk = 0; kk < 16; ++kk) {
        int k = ks * 16 + kk;
        int f = k / KW;
        int m = k - f * KW;
        v[kk] = (m == 0) ? Wb[(size_t)f * UDIM + n]
                         : Ws[(size_t)(f * 6 + m - 1) * UDIM + n];
    }
    const int bxn = n >> 7;
    const int ntl = (n >> 3) & 15;
    __half2* dst = reinterpret_cast<__half2*>(g_btf);
    size_t base = (((size_t)bxn * NKSTEP + ks) * 16 + ntl) * 64 + (n & 7) * 8;
    #pragma unroll
    for (int t = 0; t < 4; ++t) {
        dst[base + t * 2 + 0] = __floats2half2_rn(v[2 * t],     v[2 * t + 1]);
        dst[base + t * 2 + 1] = __floats2half2_rn(v[8 + 2 * t], v[8 + 2 * t + 1]);
    }
}

// ---------------------------------------------------------------------------
// closed-form cubic B-spline: 7 values (round-14 verbatim, passing)
// ---------------------------------------------------------------------------
__device__ __forceinline__ void gen7(float xv, float t0, float inv_h, float* v) {
    float xr = (xv - t0) * inv_h;
    float fi = floorf(xr);
    int   i  = (int)fi;
    float s  = xr - fi;
    float s2 = s * s, s3 = s2 * s;
    float u  = 1.0f - s;
    const float c6 = 1.0f / 6.0f;
    float B0 = c6 * u * u * u;
    float B1 = c6 * (3.0f * s3 - 6.0f * s2 + 4.0f);
    float B2 = c6 * (-3.0f * s3 + 3.0f * s2 + 3.0f * s + 1.0f);
    float B3 = c6 * s3;
    bool valid = (xr >= 0.0f) && (i <= 8);
    v[0] = fmaxf(xv, 0.0f);
    #pragma unroll
    for (int j = 0; j < 6; ++j) {
        int d = i - j;
        float bv = (d == 3) ? B0 : (d == 2) ? B1 : (d == 1) ? B2 : (d == 0) ? B3 : 0.0f;
        v[1 + j] = valid ? bv : 0.0f;
    }
}

// ---------------------------------------------------------------------------
// Kernel 2: fused LN + packed A fragments (round-14 logic; dst layout only
// change: [by][ks][mt8] instead of [mt][ks]).
// ---------------------------------------------------------------------------
__global__ __launch_bounds__(256) void afln_kernel(
    const float* __restrict__ x,
    const float* __restrict__ gamma,
    const float* __restrict__ beta,
    const float* __restrict__ grid_knots)
{
    __shared__ float sx[16][514];
    __shared__ float sg[512], sb[512];
    __shared__ float smean[16], sinv[16];
    __shared__ __align__(16) __half sstg[8][16 * 116];

    const int tid  = threadIdx.x;
    const int lane = tid & 31;
    const int wq   = tid >> 5;
    const int R0   = blockIdx.x * 16;

    const float t0    = __ldg(grid_knots);
    const float inv_h = 1.0f / (__ldg(grid_knots + 1) - t0);

    for (int idx = tid; idx < 16 * 128; idx += 256) {
        int row = idx >> 7, q = idx & 127;
        float4 v = __ldg(reinterpret_cast<const float4*>(
            x + (size_t)(R0 + row) * FDIM) + q);
        *reinterpret_cast<float2*>(&sx[row][q * 4])     = make_float2(v.x, v.y);
        *reinterpret_cast<float2*>(&sx[row][q * 4 + 2]) = make_float2(v.z, v.w);
    }
    for (int idx = tid; idx < 512; idx += 256) {
        sg[idx] = __ldg(gamma + idx);
        sb[idx] = __ldg(beta + idx);
    }
    __syncthreads();

    #pragma unroll
    for (int rr = 0; rr < 2; ++rr) {
        int r = wq * 2 + rr;
        float s = 0.0f;
        #pragma unroll
        for (int i = 0; i < 16; ++i) s += sx[r][lane + 32 * i];
        #pragma unroll
        for (int o = 16; o > 0; o >>= 1) s += __shfl_xor_sync(~0u, s, o);
        float mean = s * (1.0f / FDIM);
        float s2 = 0.0f;
        #pragma unroll
        for (int i = 0; i < 16; ++i) {
            float d = sx[r][lane + 32 * i] - mean;
            s2 += d * d;
        }
        #pragma unroll
        for (int o = 16; o > 0; o >>= 1) s2 += __shfl_xor_sync(~0u, s2, o);
        if (lane == 0) {
            smean[r] = mean;
            sinv[r]  = rsqrtf(s2 * (1.0f / FDIM) + 1e-3f);
        }
    }
    __syncthreads();

    const int rl = lane & 15;
    const int ph = lane >> 4;
    const int g7 = lane >> 2;
    const int tq = lane & 3;
    const float mean = smean[rl];
    const float inv  = sinv[rl];

    __half* stg = &sstg[wq][rl * 116];
    const __half* stgW = sstg[wq];
    // dst: [by][ks][mtl][32 uint4]; by = bx>>3, mtl = bx&7
    uint4* dstB = reinterpret_cast<uint4*>(g_af) +
                  (((size_t)(blockIdx.x >> 3) * NKSTEP * 8) +
                   (blockIdx.x & 7)) * 32 + SIG(lane);

    #pragma unroll 1
    for (int g = wq; g < 32; g += 8) {
        #pragma unroll
        for (int q = 0; q < 4; ++q) {
            int fp  = q * 4 + ph * 2;
            int col = g * 16 + fp;
            float xa = (sx[rl][col]     - mean) * inv * sg[col]     + sb[col];
            float xb = (sx[rl][col + 1] - mean) * inv * sg[col + 1] + sb[col + 1];
            float va[7], vb[7];
            gen7(xa, t0, inv_h, va);
            gen7(xb, t0, inv_h, vb);
            __half2* w = reinterpret_cast<__half2*>(stg + fp * KW);
            w[0] = __floats2half2_rn(va[0], va[1]);
            w[1] = __floats2half2_rn(va[2], va[3]);
            w[2] = __floats2half2_rn(va[4], va[5]);
            w[3] = __floats2half2_rn(va[6], vb[0]);
            w[4] = __floats2half2_rn(vb[1], vb[2]);
            w[5] = __floats2half2_rn(vb[3], vb[4]);
            w[6] = __floats2half2_rn(vb[5], vb[6]);
        }
        __syncwarp();
        #pragma unroll
        for (int j = 0; j < KW; ++j) {
            int kl = j * 16 + 2 * tq;
            uint32_t w0 = *reinterpret_cast<const uint32_t*>(&stgW[g7 * 116 + kl]);
            uint32_t w1 = *reinterpret_cast<const uint32_t*>(&stgW[(g7 + 8) * 116 + kl]);
            uint32_t w2 = *reinterpret_cast<const uint32_t*>(&stgW[g7 * 116 + kl + 8]);
            uint32_t w3 = *reinterpret_cast<const uint32_t*>(&stgW[(g7 + 8) * 116 + kl + 8]);
            // kstep = g*KW + j; stride between ksteps = 8 mt blocks * 32 uint4
            dstB[(size_t)(g * KW + j) * 256] = make_uint4(w0, w1, w2, w3);
        }
        __syncwarp();
    }
}

// ---------------------------------------------------------------------------
// Kernel 3: bulk-copy 3-stage pipelined HMMA GEMM — 2 x 16KB contiguous
// copies per stage, single-thread issue. smem layout [ks][mt]/[ks][nt].
// ---------------------------------------------------------------------------
__global__ __launch_bounds__(256, 2) void kan_mma_kernel(
    const float* __restrict__ bias, float* __restrict__ out)
{
    extern __shared__ __align__(16) char smem[];
    const uint32_t sbase = smem_u32(smem);

    const int tid  = threadIdx.x;
    const int lane = tid & 31;
    const int wid  = tid >> 5;
    const int wm   = wid >> 2;
    const int wn   = wid & 3;
    const int row0 = blockIdx.y * 128;
    const int col0 = blockIdx.x * 128;

    const char* asrc = reinterpret_cast<const char*>(g_af) +
                       (size_t)blockIdx.y * NKSTEP * 4096;
    const char* bsrc = reinterpret_cast<const char*>(g_btf) +
                       (size_t)blockIdx.x * NKSTEP * 4096;

    if (tid == 0) {
        #pragma unroll
        for (int s = 0; s < NSTG; ++s) MBAR_INIT(sbase + SM_MBAR + s * 8, 1);
        FENCE_ASYNC();
    }
    __syncthreads();

    auto issue_stage = [&](int stg, int ks0) {
        if (tid == 0) {
            const uint32_t mb = sbase + SM_MBAR + stg * 8;
            const uint32_t da = sbase + stg * STG_BYTES;
            MBAR_EXPECT_TX(mb, STG_BYTES);
            CP_BULK(da,         asrc + (size_t)ks0 * 4096, 16384, mb);
            CP_BULK(da + 16384, bsrc + (size_t)ks0 * 4096, 16384, mb);
        }
    };

    float acc[4][4][4];
    #pragma unroll
    for (int in = 0; in < 4; ++in) {
        float2 bb = *reinterpret_cast<const float2*>(
            bias + col0 + wn * 32 + in * 8 + (lane & 3) * 2);
        #pragma unroll
        for (int im = 0; im < 4; ++im) {
            acc[im][in][0] = bb.x; acc[im][in][1] = bb.y;
            acc[im][in][2] = bb.x; acc[im][in][3] = bb.y;
        }
    }

    issue_stage(0, 0);
    issue_stage(1, BIG);

    const int aslot = SIG(lane);
    int phs[NSTG] = {0, 0, 0};
    int stg = 0;
    for (int it = 0; it < NIT; ++it) {
        MBAR_WAIT(sbase + SM_MBAR + stg * 8, phs[stg]);
        phs[stg] ^= 1;

        const char* sa = smem + stg * STG_BYTES;
        const char* sb = sa + 16384;
        #pragma unroll
        for (int ks = 0; ks < BIG; ++ks) {
            uint4 a[4];
            #pragma unroll
            for (int im = 0; im < 4; ++im)
                a[im] = *reinterpret_cast<const uint4*>(
                    sa + ((ks * 8 + wm * 4 + im) * 32 + aslot) * 16);
            uint2 b[4];
            #pragma unroll
            for (int in = 0; in < 4; ++in)
                b[in] = *reinterpret_cast<const uint2*>(
                    sb + ((ks * 16 + wn * 4 + in) * 32 + lane) * 8);
            #pragma unroll
            for (int im = 0; im < 4; ++im)
                #pragma unroll
                for (int in = 0; in < 4; ++in) {
                    asm volatile(
                        "mma.sync.aligned.m16n8k16.row.col.f32.f16.f16.f32 "
                        "{%0,%1,%2,%3}, {%4,%5,%6,%7}, {%8,%9}, {%0,%1,%2,%3};"
                        : "+f"(acc[im][in][0]), "+f"(acc[im][in][1]),
                          "+f"(acc[im][in][2]), "+f"(acc[im][in][3])
                        : "r"(a[im].x), "r"(a[im].y), "r"(a[im].z), "r"(a[im].w),
                          "r"(b[in].x), "r"(b[in].y));
                }
        }

        __syncthreads();   // all warps done reading stage (stg+2)%3's old data
        if (it + 2 < NIT) issue_stage((stg + 2) % NSTG, (it + 2) * BIG);
        stg = (stg + 1) % NSTG;
    }

    const int g  = lane >> 2;
    const int tq = lane & 3;
    #pragma unroll
    for (int im = 0; im < 4; ++im) {
        int row = row0 + wm * 64 + im * 16 + g;
        #pragma unroll
        for (int in = 0; in < 4; ++in) {
            int col = col0 + wn * 32 + in * 8 + tq * 2;
            *reinterpret_cast<float2*>(out + (size_t)row * UDIM + col)
                = make_float2(acc[im][in][0], acc[im][in][1]);
            *reinterpret_cast<float2*>(out + (size_t)(row + 8) * UDIM + col)
                = make_float2(acc[im][in][2], acc[im][in][3]);
        }
    }
}

// ---------------------------------------------------------------------------
extern "C" void kernel_launch(void* const* d_in, const int* in_sizes, int n_in,
                              void* d_out, int out_size) {
    const float* x     = (const float*)d_in[0];
    const float* gamma = (const float*)d_in[1];
    const float* beta  = (const float*)d_in[2];
    const float* Wb    = (const float*)d_in[3];
    const float* bias  = (const float*)d_in[4];
    const float* Ws    = (const float*)d_in[5];
    const float* grid  = (const float*)d_in[6];
    float* out = (float*)d_out;

    static cudaStream_t s1 = nullptr;
    static cudaEvent_t ev0, evb;
    if (s1 == nullptr) {
        cudaStreamCreateWithFlags(&s1, cudaStreamNonBlocking);
        cudaEventCreateWithFlags(&ev0, cudaEventDisableTiming);
        cudaEventCreateWithFlags(&evb, cudaEventDisableTiming);
        cudaFuncSetAttribute(kan_mma_kernel,
                             cudaFuncAttributeMaxDynamicSharedMemorySize,
                             SMEM_TOTAL);
    }

    // fork: btf on s1 overlaps afln on the main stream
    cudaEventRecord(ev0, 0);
    cudaStreamWaitEvent(s1, ev0, 0);
    btf_kernel<<<dim3(2, NKSTEP), 256, 0, s1>>>(Wb, Ws);
    cudaEventRecord(evb, s1);

    afln_kernel<<<NROWS / 16, 256>>>(x, gamma, beta, grid);

    cudaStreamWaitEvent(0, evb, 0);
    kan_mma_kernel<<<dim3(UDIM / 128, NROWS / 128), 256, SMEM_TOTAL>>>(bias, out);
}